// round 9
// baseline (speedup 1.0000x reference)
#include <cuda_runtime.h>

#define SX 512
#define NG (SX * SX)
#define NW (NG / 32)
#define MAXM 8192

// ---- persistent device state (self-cleaning across graph replays):
//  - g_occ: set in K1, cleared in K4 (after last read)       -> clean at K1 entry
//  - g_counts: cleared at top of K1 (first written in K4)    -> clean at K4 entry
//  - g_ctr: zeroed by warp0 at end of K5                     -> clean at K1 entry
//  - g_cid: NEVER cleared; every read is guarded by a freshly built occ bit
//  - all other arrays fully rewritten for indices < M each call
__device__ int      g_cid[NG];     // voxel id -> compact id (this run)
__device__ unsigned g_occ[NW];     // occupancy bitmap
__device__ int      g_vox[MAXM];   // cid -> voxel id
__device__ int      g_parent[MAXM];// union-find parent
__device__ unsigned char g_isc[MAXM]; // cid -> is-core
__device__ int      g_rawv[MAXM];  // cid -> raw root voxel id (or -1)
__device__ int      g_dense[MAXM]; // cid -> dense id (or -1)
__device__ int      g_counts[MAXM];// dense id -> voxel count
__device__ int      g_roots[MAXM]; // collected root voxel ids (unordered)
__device__ int      g_pvox[MAXM];  // point -> voxel id
__device__ int      g_ctr[2];      // [0]=M  [1]=R

// voxelization: must match jnp floor((p - (-51.2)) / 0.2) in fp32 (identical
// expression to previously-passing kernels — do not alter rounding behavior)
__device__ __forceinline__ int voxel_of(float px, float py) {
    int cx = (int)floorf((px - (-51.2f)) / 0.2f);
    int cy = (int)floorf((py - (-51.2f)) / 0.2f);
    cx = min(max(cx, 0), SX - 1);
    cy = min(max(cy, 0), SX - 1);
    return cy * SX + cx;
}

__device__ __forceinline__ bool occbit(int x, int y) {
    if ((unsigned)x >= SX || (unsigned)y >= SX) return false;
    int v = y * SX + x;
    return (g_occ[v >> 5] >> (v & 31)) & 1u;
}

// core = occupied && >=5 occupied in 3x3 (eps=1.5 => 8-neighborhood, self incl).
// Caller guarantees (x,y) occupied OR guards with occbit.
__device__ __forceinline__ bool corecell(int x, int y) {
    int cnt = 0;
    #pragma unroll
    for (int dy = -1; dy <= 1; dy++)
        #pragma unroll
        for (int dx = -1; dx <= 1; dx++)
            cnt += (int)occbit(x + dx, y + dy);
    return cnt >= 5;
}

// find with path halving — used ONLY inside k_union; races quiesce at the
// kernel boundary. __ldcg chase loads avoid spinning on a stale L1 line;
// CAS return values guarantee forward progress. Hooking compares VOXEL ids,
// so final roots are component minima regardless of schedule / cid order.
__device__ int ffind(int x) {
    while (true) {
        int p = __ldcg(&g_parent[x]);
        if (p == x) return x;
        int gp = __ldcg(&g_parent[p]);
        if (gp != p) g_parent[x] = gp;   // benign race
        x = p;
    }
}

__device__ void funite(int a, int b) {
    int ra = ffind(a), rb = ffind(b);
    while (ra != rb) {
        if (g_vox[ra] < g_vox[rb]) { int t = ra; ra = rb; rb = t; }
        int prev = atomicCAS(&g_parent[ra], ra, rb); // hook larger-vox root under smaller
        if (prev == ra) return;
        ra = ffind(prev);
        rb = ffind(rb);
    }
}

// read-only chase (parent static after k_union => deterministic)
__device__ __forceinline__ int chase(int x) {
    int p = g_parent[x];
    while (p != x) { x = p; p = g_parent[x]; }
    return x;
}

// K1: clear counts; voxelize; occupancy; warp-aggregated compact append
__global__ void k_vox(const float* __restrict__ pts, int N) {
    int i = blockIdx.x * blockDim.x + threadIdx.x;
    int lane = threadIdx.x & 31;
    if (i < MAXM) g_counts[i] = 0;

    int v = 0; bool app = false;
    if (i < N) {
        v = voxel_of(pts[i * 5 + 1], pts[i * 5 + 2]);
        g_pvox[i] = v;
        unsigned m = 1u << (v & 31);
        unsigned old = atomicOr(&g_occ[v >> 5], m);
        app = !(old & m);
    }
    unsigned ball = __ballot_sync(0xffffffffu, app);
    if (ball) {
        int leader = __ffs(ball) - 1;
        int base = 0;
        if (lane == leader) base = atomicAdd(&g_ctr[0], __popc(ball));
        base = __shfl_sync(0xffffffffu, base, leader);
        if (app) {
            int c = base + __popc(ball & ((1u << lane) - 1u));
            g_vox[c] = v;
            g_cid[v] = c;
            g_parent[c] = c;
        }
    }
}

// K2: per cid: core flag (on-the-fly from occ) + union over core-core
//     back-edges (each undirected 8-edge processed exactly once)
__global__ void k_union() {
    int c = blockIdx.x * blockDim.x + threadIdx.x;
    int M = g_ctr[0];
    if (c >= M) return;
    int v = g_vox[c], x = v & (SX - 1), y = v >> 9;
    bool sc = corecell(x, y);
    g_isc[c] = sc;
    if (!sc) return;
    const int dd[4][2] = {{-1, 0}, {-1, -1}, {0, -1}, {1, -1}};
    #pragma unroll
    for (int k = 0; k < 4; k++) {
        int nx = x + dd[k][0], ny = y + dd[k][1];
        if (occbit(nx, ny) && corecell(nx, ny))
            funite(c, g_cid[ny * SX + nx]);
    }
}

// K3: flatten (read-only) + raw labels + root collection
__global__ void k_label() {
    int c = blockIdx.x * blockDim.x + threadIdx.x;
    int M = g_ctr[0];
    if (c >= M) return;
    int v = g_vox[c];
    if (g_isc[c]) {
        int rc = chase(c);
        g_rawv[c] = g_vox[rc];
        if (rc == c) { int idx = atomicAdd(&g_ctr[1], 1); g_roots[idx] = v; }
    } else {
        int best = 0x7fffffff;
        int x = v & (SX - 1), y = v >> 9;
        #pragma unroll
        for (int dy = -1; dy <= 1; dy++)
            #pragma unroll
            for (int dx = -1; dx <= 1; dx++) {
                if (dx == 0 && dy == 0) continue;
                int nx = x + dx, ny = y + dy;
                if (!occbit(nx, ny)) continue;
                int nc = g_cid[ny * SX + nx];
                if (g_isc[nc]) best = min(best, g_vox[chase(nc)]);
            }
        g_rawv[c] = (best == 0x7fffffff) ? -1 : best;
    }
}

// K4: dense id = rank of root voxel among all root voxels (order-invariant
//     wrt append order); accumulate per-cluster voxel counts; clear occ words
//     (occ is dead after this kernel -> clean for the next call)
__global__ void k_rank() {
    int c = blockIdx.x * blockDim.x + threadIdx.x;
    int M = g_ctr[0];
    if (c >= M) return;
    int R = g_ctr[1];
    int rv = g_rawv[c];
    int d = -1;
    if (rv >= 0) {
        int rank = 0;
        for (int j = 0; j < R; j++) rank += (g_roots[j] < rv);
        d = rank;
        atomicAdd(&g_counts[d], 1);
    }
    g_dense[c] = d;
    g_occ[g_vox[c] >> 5] = 0;   // all writers write 0: race-free cleanup
}

// K5: per-point final label; warp0 of block0: max_num_inst from counts and
//     counter reset (only warp0 touches g_ctr here -> race-free)
__global__ void k_out(int N, float* __restrict__ out, int out_size) {
    int i = blockIdx.x * blockDim.x + threadIdx.x;
    if (i < N) {
        int c = g_cid[g_pvox[i]];
        int d = g_dense[c];
        int f = (d >= 0 && g_counts[d] >= 20) ? d : -1;
        out[i] = (float)f;
    }
    if (blockIdx.x == 0 && threadIdx.x < 32) {
        int lane = threadIdx.x;
        int R = g_ctr[1];
        int m = 0;
        for (int d = lane; d < R; d += 32)
            if (g_counts[d] >= 20) m = max(m, d + 1);
        m = __reduce_max_sync(0xffffffffu, m);
        if (lane == 0) {
            if (out_size > N) out[N] = (float)m;
            g_ctr[0] = 0;            // self-clean for next call
            g_ctr[1] = 0;
        }
    }
}

extern "C" void kernel_launch(void* const* d_in, const int* in_sizes, int n_in,
                              void* d_out, int out_size) {
    const float* pts = (const float*)d_in[0];
    int N = in_sizes[0] / 5;
    if (N > MAXM) N = MAXM;
    float* out = (float*)d_out;

    const int T = 256;
    const int NB = (MAXM + T - 1) / T;              // covers both N and M domains
    k_vox  <<<(max(N, MAXM) + T - 1) / T, T>>>(pts, N);
    k_union<<<NB, T>>>();
    k_label<<<NB, T>>>();
    k_rank <<<NB, T>>>();
    k_out  <<<(N + T - 1) / T, T>>>(N, out, out_size);
}

// round 12
// speedup vs baseline: 1.6319x; 1.6319x over previous
#include <cuda_runtime.h>

#define SX 512
#define NG (SX * SX)
#define NW (NG / 32)      // 8192 bitmap words
#define MAXN 8192

// ---- persistent device state (self-cleaning across graph replays):
//  g_occ/g_corb bitmaps : set this run, cleared by k_out (not read there)
//  g_counts             : cleared in k_occ (first written in k_count)
//  g_rctr               : reset by k_out thread 0 (after last read)
//  g_parent             : initialized at core cells by k_core each run
//  g_rootlab/g_raw/g_dense/g_voxd : stale entries unreachable (reads guarded
//                         by freshly built occ/core bits of the current run)
__device__ unsigned g_occ[NW];
__device__ unsigned g_corb[NW];
__device__ int g_parent[NG];
__device__ int g_rootlab[NG];   // core cell -> component-min cell index
__device__ int g_raw[NG];       // occupied cell -> raw root cell index (or -1)
__device__ int g_dense[NG];     // root cell -> dense id
__device__ int g_voxd[NG];      // occupied cell -> dense id (or -1)
__device__ int g_counts[MAXN];  // dense id -> voxel count
__device__ int g_roots[MAXN];   // collected root cell indices (unordered)
__device__ int g_pvox[MAXN];    // point -> voxel id
__device__ int g_rctr;          // number of roots R

// voxelization: must match jnp floor((p - (-51.2)) / 0.2) in fp32
__device__ __forceinline__ int voxel_of(float px, float py) {
    int cx = (int)floorf((px - (-51.2f)) / 0.2f);
    int cy = (int)floorf((py - (-51.2f)) / 0.2f);
    cx = min(max(cx, 0), SX - 1);
    cy = min(max(cy, 0), SX - 1);
    return cy * SX + cx;
}

__device__ __forceinline__ bool bit(const unsigned* bm, int v) {
    return (bm[v >> 5] >> (v & 31)) & 1u;
}

// ---- union-find, R3-proven form (races quiesce at kernel boundary; hooking
// compares cell indices so final roots are component minima) ----
__device__ int ffind(int x) {
    while (true) {
        int p = g_parent[x];
        if (p == x) return x;
        int gp = g_parent[p];
        if (gp != p) g_parent[x] = gp;   // path halving (benign race)
        x = p;
    }
}

__device__ void funite(int a, int b) {
    int ra = ffind(a), rb = ffind(b);
    while (ra != rb) {
        if (ra < rb) { int t = ra; ra = rb; rb = t; }
        int prev = atomicCAS(&g_parent[ra], ra, rb);  // hook larger under smaller
        if (prev == ra) return;
        ra = ffind(prev);
        rb = ffind(rb);
    }
}

// K1: clear counts (dead since last k_count) + voxelize + occupancy
__global__ void k_occ(const float* __restrict__ pts, int N) {
    int i = blockIdx.x * blockDim.x + threadIdx.x;
    if (i < MAXN) g_counts[i] = 0;
    if (i < N) {
        int v = voxel_of(pts[i * 5 + 1], pts[i * 5 + 2]);
        g_pvox[i] = v;
        atomicOr(&g_occ[v >> 5], 1u << (v & 31));
    }
}

// K2: core = occupied && >=5 occupied in 3x3 (eps=1.5 => 8-neighborhood,
// self incl); init parent at core cells
__global__ void k_core() {
    int i = blockIdx.x * blockDim.x + threadIdx.x;
    if (i >= NG) return;
    if (!bit(g_occ, i)) return;
    int x = i & (SX - 1), y = i >> 9;
    int cnt = 0;
    #pragma unroll
    for (int dy = -1; dy <= 1; dy++) {
        int ny = y + dy;
        if ((unsigned)ny >= SX) continue;
        #pragma unroll
        for (int dx = -1; dx <= 1; dx++) {
            int nx = x + dx;
            if ((unsigned)nx >= SX) continue;
            cnt += (int)bit(g_occ, ny * SX + nx);
        }
    }
    if (cnt >= 5) {
        atomicOr(&g_corb[i >> 5], 1u << (i & 31));
        g_parent[i] = i;
    }
}

// K3: union over core-core 8-edges (each undirected edge once)
__global__ void k_union() {
    int i = blockIdx.x * blockDim.x + threadIdx.x;
    if (i >= NG) return;
    if (!bit(g_corb, i)) return;
    int x = i & (SX - 1), y = i >> 9;
    if (x > 0 && bit(g_corb, i - 1)) funite(i, i - 1);
    if (y > 0) {
        if (x > 0 && bit(g_corb, i - SX - 1)) funite(i, i - SX - 1);
        if (bit(g_corb, i - SX))              funite(i, i - SX);
        if (x < SX - 1 && bit(g_corb, i - SX + 1)) funite(i, i - SX + 1);
    }
}

// K4: flatten READ-ONLY (parent static => deterministic) + collect roots
__global__ void k_flatten() {
    int i = blockIdx.x * blockDim.x + threadIdx.x;
    if (i >= NG) return;
    if (!bit(g_corb, i)) return;
    int xx = i, p = g_parent[xx];
    while (p != xx) { xx = p; p = g_parent[xx]; }
    g_rootlab[i] = xx;
    if (xx == i) { int idx = atomicAdd(&g_rctr, 1); g_roots[idx] = i; }
}

// K5: raw label per occupied cell + dense rank at root cells
//     (rank = #roots with smaller cell index; order-invariant wrt append order)
__global__ void k_rankraw() {
    int i = blockIdx.x * blockDim.x + threadIdx.x;
    if (i >= NG) return;
    if (!bit(g_occ, i)) return;
    if (bit(g_corb, i)) {
        int r = g_rootlab[i];
        g_raw[i] = r;
        if (r == i) {
            int R = g_rctr, rank = 0;
            for (int j = 0; j < R; j++) rank += (g_roots[j] < i);
            g_dense[i] = rank;
        }
    } else {
        int best = 0x7fffffff;
        int x = i & (SX - 1), y = i >> 9;
        #pragma unroll
        for (int dy = -1; dy <= 1; dy++) {
            int ny = y + dy;
            if ((unsigned)ny >= SX) continue;
            #pragma unroll
            for (int dx = -1; dx <= 1; dx++) {
                int nx = x + dx;
                if ((unsigned)nx >= SX) continue;
                int n = ny * SX + nx;
                if (bit(g_corb, n)) best = min(best, g_rootlab[n]);
            }
        }
        g_raw[i] = (best == 0x7fffffff) ? -1 : best;
    }
}

// K6: per-cell dense id + per-cluster voxel counts
__global__ void k_count() {
    int i = blockIdx.x * blockDim.x + threadIdx.x;
    if (i >= NG) return;
    if (!bit(g_occ, i)) return;
    int r = g_raw[i];
    if (r >= 0) {
        int d = g_dense[r];
        g_voxd[i] = d;
        atomicAdd(&g_counts[d], 1);
    } else {
        g_voxd[i] = -1;
    }
}

// K7: per-point final label; block0 warp0: max_num_inst + counter reset;
//     all threads: clear one occ/corb word each (not read in this kernel)
__global__ void k_out(int N, float* __restrict__ out, int out_size) {
    int i = blockIdx.x * blockDim.x + threadIdx.x;
    if (i < N) {
        int v = g_pvox[i];
        int d = g_voxd[v];
        int f = (d >= 0 && g_counts[d] >= 20) ? d : -1;
        out[i] = (float)f;
    }
    if (i < NW) { g_occ[i] = 0; g_corb[i] = 0; }
    if (blockIdx.x == 0 && threadIdx.x < 32) {
        int lane = threadIdx.x;
        int R = g_rctr;
        int m = 0;
        for (int d = lane; d < R; d += 32)
            if (g_counts[d] >= 20) m = max(m, d + 1);
        m = __reduce_max_sync(0xffffffffu, m);
        if (lane == 0) {
            if (out_size > N) out[N] = (float)m;
            g_rctr = 0;               // self-clean for next replay
        }
    }
}

extern "C" void kernel_launch(void* const* d_in, const int* in_sizes, int n_in,
                              void* d_out, int out_size) {
    const float* pts = (const float*)d_in[0];
    int N = in_sizes[0] / 5;
    if (N > MAXN) N = MAXN;
    float* out = (float*)d_out;

    const int T = 256;
    const int GB = (NG + T - 1) / T;           // 1024 blocks: full-grid passes
    const int SB = (MAXN + T - 1) / T;         // 32 blocks: point/word passes
    k_occ    <<<SB, T>>>(pts, N);
    k_core   <<<GB, T>>>();
    k_union  <<<GB, T>>>();
    k_flatten<<<GB, T>>>();
    k_rankraw<<<GB, T>>>();
    k_count  <<<GB, T>>>();
    k_out    <<<SB, T>>>(N, out, out_size);
}